// round 11
// baseline (speedup 1.0000x reference)
#include <cuda_runtime.h>

// 12-qubit, 4-layer variational circuit simulator — R7.
// R7 vs R5 (22.3us): latency-hiding attack. issue was 35.7% with 4 warps/SMSP.
//  - 8 amps/thread x 512 threads (was 16 x 256): regs ~64 -> 2 CTAs/SM = 8 warps/SMSP
//  - each pass: 3 qubits register-local (k bits) + 1 qubit via __shfl_xor on a
//    lane bit (same fma count, zero smem traffic)
//  - ping-pong state buffers (dynamic smem, 2x32KB): perm pass reads prev buffer,
//    writes next -> one barrier instead of read/sync/write; 3 barriers/layer
//  - retained: f32x2 math, fused-RZ pass diagonals, separable data diagonal,
//    CX ladder as index permutation fused into loads, layer-0 from constant state.

#define DIM 4096
#define NT  512
typedef unsigned long long u64;

__device__ __forceinline__ int phys(int i) { return i ^ ((i >> 4) & 15); }

__device__ __forceinline__ u64 pk2(float lo, float hi) {
    u64 r;
    asm("mov.b64 %0, {%1, %2};" : "=l"(r)
        : "r"(__float_as_uint(lo)), "r"(__float_as_uint(hi)));
    return r;
}
__device__ __forceinline__ void upk(u64 v, float& lo, float& hi) {
    unsigned a, b;
    asm("mov.b64 {%0, %1}, %2;" : "=r"(a), "=r"(b) : "l"(v));
    lo = __uint_as_float(a);
    hi = __uint_as_float(b);
}
__device__ __forceinline__ u64 swp(u64 v) {
    unsigned a, b;
    asm("mov.b64 {%0, %1}, %2;" : "=r"(a), "=r"(b) : "l"(v));
    u64 r;
    asm("mov.b64 %0, {%1, %2};" : "=l"(r) : "r"(b), "r"(a));
    return r;
}
__device__ __forceinline__ u64 mul2(u64 a, u64 b) {
    u64 r;
    asm("mul.rn.f32x2 %0, %1, %2;" : "=l"(r) : "l"(a), "l"(b));
    return r;
}
__device__ __forceinline__ u64 fma2(u64 a, u64 b, u64 c) {
    u64 r;
    asm("fma.rn.f32x2 %0, %1, %2, %3;" : "=l"(r) : "l"(a), "l"(b), "l"(c));
    return r;
}
// a * (pr + i*pi); phase pre-splatted r2=(pr,pr), n=(-pi,pi); a packed (re,im).
__device__ __forceinline__ u64 pmul(u64 a, u64 r2, u64 n) {
    return fma2(r2, a, mul2(n, swp(a)));
}

struct GY { u64 c2, s2, ns2; };  // (c,c) (s,s) (-s,-s)

__device__ __forceinline__ void ry2(u64& a0, u64& a1, const GY g) {
    u64 t0 = fma2(g.c2, a0, mul2(g.ns2, a1));
    u64 t1 = fma2(g.s2, a0, mul2(g.c2, a1));
    a0 = t0; a1 = t1;
}
// RYs on the 3 k-bits (bit0..bit2) of a[8].
__device__ __forceinline__ void ry3(u64* a, const GY* gs) {
    const GY g0 = gs[0], g1 = gs[1], g2 = gs[2];
    #pragma unroll
    for (int k = 0; k < 8; k += 2) ry2(a[k], a[k + 1], g0);
    #pragma unroll
    for (int k = 0; k < 8; k++) if (!(k & 2)) ry2(a[k], a[k | 2], g1);
    #pragma unroll
    for (int k = 0; k < 4; k++) ry2(a[k], a[k | 4], g2);
}
// RY on a lane-bit qubit via shfl_xor. ss = side ? (s,s) : (-s,-s).
__device__ __forceinline__ void rysh(u64* a, u64 c2, u64 ss, unsigned m) {
    #pragma unroll
    for (int k = 0; k < 8; k++) {
        u64 p = __shfl_xor_sync(0xffffffffu, a[k], m);
        a[k] = fma2(c2, a[k], mul2(ss, p));
    }
}
// Fused trainable-RZ diagonal for a pass (3 k-bits + side already folded in dP).
__device__ __forceinline__ void diag8(u64* a, const ulonglong2* dP) {
    #pragma unroll
    for (int k = 0; k < 8; k++) { ulonglong2 d = dP[k]; a[k] = pmul(a[k], d.x, d.y); }
}

__global__ void __launch_bounds__(NT, 2)
qsim_kernel(const float* __restrict__ x, const float* __restrict__ w,
            float* __restrict__ out) {
    extern __shared__ u64 amp[];        // [2][DIM] ping-pong state, swizzled
    __shared__ GY gy[48];               // RY splats
    __shared__ ulonglong2 gd[12 * 16];  // per-(layer,pass) fused-RZ diag splats,
                                        // index m = (side<<3)|k over the 4 pass qubits
    __shared__ ulonglong2 tl[64];       // data-diag qubits 0..5 splats
    __shared__ ulonglong2 th[64];       // data-diag qubits 6..11 splats
    __shared__ float red[16];

    const int tid = threadIdx.x;
    const float* xv = x + blockIdx.x * 12;

    // ---- precompute: one sincos per thread-slot ----
    if (tid < 48) {                     // RY gate splats
        float c, s;
        sincosf(0.5f * w[2 * tid], &s, &c);
        gy[tid].c2 = pk2(c, c);
        gy[tid].s2 = pk2(s, s);
        gy[tid].ns2 = pk2(-s, -s);
    }
    if (tid >= 64 && tid < 192) {       // separable data-diagonal tables
        int m = (tid - 64) & 63;
        const float* xs = xv + ((tid >= 128) ? 6 : 0);
        float a = 0.f;
        #pragma unroll
        for (int q = 0; q < 6; q++) a += ((m >> q) & 1) ? xs[q] : -xs[q];
        a *= 0.5f;
        float sn, cs;
        sincosf(a, &sn, &cs);
        ulonglong2 e = make_ulonglong2(pk2(cs, cs), pk2(-sn, sn));
        if (tid < 128) tl[m] = e; else th[m] = e;
    }
    if (tid >= 256 && tid < 448) {      // fused trainable-RZ diagonals, 12 passes x 16
        int idx = tid - 256;
        int p = idx >> 4, m = idx & 15;
        int layer = p / 3, qb = (p % 3) * 4;
        const float* wz = w + 2 * (layer * 12 + qb);
        float t = 0.f;
        #pragma unroll
        for (int j = 0; j < 4; j++)
            t += (((m >> j) & 1) ? 0.5f : -0.5f) * wz[2 * j + 1];
        float di, dr;
        sincosf(t, &di, &dr);
        gd[idx] = make_ulonglong2(pk2(dr, dr), pk2(-di, di));
    }
    __syncthreads();

    // pass mappings (i = state index, t = tid, k = 0..7):
    //  A: i = (t<<3)|k            local q0,1,2; shfl q3  <-> t bit0 (mask 1)
    //  B: i = (t&15)|(k<<4)|((t>>4)<<7)   local q4,5,6; shfl q7  <-> t bit4 (mask 16)
    //  C: i = (t&15)|((t>>5)&15)<<4|(k<<8)|((t>>4)&1)<<11  local q8,9,10; shfl q11 (mask 16)
    const int sideA = tid & 1;
    const int sideB = (tid >> 4) & 1;
    const int baseB = (tid & 15) | ((tid >> 4) << 7);
    const int baseC = (tid & 15) | (((tid >> 5) & 15) << 4) | (((tid >> 4) & 1) << 11);
    const ulonglong2 hsp = th[tid >> 3];      // i>>6 data phase, thread-constant in pass A
    const int tlB = (tid & 7) << 3;           // tl index base in pass A

    u64* buf0 = amp;
    u64* buf1 = amp + DIM;
    u64 a[8];

    // ---- layer 0 pass A: constant state * data diag, RY q0..2, shfl q3, RZ diag ----
    {
        const u64 C = pk2(0.015625f, 0.f);
        #pragma unroll
        for (int k = 0; k < 8; k++) {
            ulonglong2 t = tl[tlB | k];
            a[k] = pmul(pmul(C, t.x, t.y), hsp.x, hsp.y);
        }
        ry3(a, gy);
        rysh(a, gy[3].c2, sideA ? gy[3].s2 : gy[3].ns2, 1u);
        diag8(a, gd + (sideA << 3));
        #pragma unroll
        for (int k = 0; k < 8; k++) buf0[phys((tid << 3) | k)] = a[k];
        __syncthreads();
    }

    #pragma unroll
    for (int l = 0; l < 4; l++) {
        u64* cur = (l & 1) ? buf1 : buf0;
        const GY* g = gy + l * 12;

        // ---- pass B: qubits 4..7 ----
        #pragma unroll
        for (int k = 0; k < 8; k++) a[k] = cur[phys(baseB | (k << 4))];
        ry3(a, g + 4);
        rysh(a, g[7].c2, sideB ? g[7].s2 : g[7].ns2, 16u);
        diag8(a, gd + (l * 3 + 1) * 16 + (sideB << 3));
        #pragma unroll
        for (int k = 0; k < 8; k++) cur[phys(baseB | (k << 4))] = a[k];
        __syncthreads();

        // ---- pass C: qubits 8..11 ----
        #pragma unroll
        for (int k = 0; k < 8; k++) a[k] = cur[phys(baseC | (k << 8))];
        ry3(a, g + 8);
        rysh(a, g[11].c2, sideB ? g[11].s2 : g[11].ns2, 16u);
        diag8(a, gd + (l * 3 + 2) * 16 + (sideB << 3));
        #pragma unroll
        for (int k = 0; k < 8; k++) cur[phys(baseC | (k << 8))] = a[k];
        __syncthreads();

        // ---- next layer pass A: CX perm fused into load from cur, write other buffer ----
        if (l < 3) {
            u64* nxt = (l & 1) ? buf0 : buf1;
            #pragma unroll
            for (int k = 0; k < 8; k++) {
                int i = (tid << 3) | k;
                int j = i ^ ((i << 1) & 0xFFE);       // composed CX ladder
                a[k] = cur[phys(j)];
            }
            #pragma unroll
            for (int k = 0; k < 8; k++) {
                ulonglong2 t = tl[tlB | k];
                a[k] = pmul(pmul(a[k], t.x, t.y), hsp.x, hsp.y);
            }
            ry3(a, g + 12);
            rysh(a, g[15].c2, sideA ? g[15].s2 : g[15].ns2, 1u);
            diag8(a, gd + (l + 1) * 3 * 16 + (sideA << 3));
            #pragma unroll
            for (int k = 0; k < 8; k++) nxt[phys((tid << 3) | k)] = a[k];
            __syncthreads();
        }
    }

    // ---- measurement: <Z(0)> with final CX perm fused into the load (state in buf1) ----
    float acc = 0.f;
    #pragma unroll
    for (int k = 0; k < 8; k++) {
        int i = (tid << 3) | k;
        int j = i ^ ((i << 1) & 0xFFE);
        float re, im;
        upk(buf1[phys(j)], re, im);
        float p = re * re + im * im;
        acc += (k & 1) ? -p : p;
    }
    #pragma unroll
    for (int off = 16; off > 0; off >>= 1)
        acc += __shfl_down_sync(0xffffffffu, acc, off);
    if ((tid & 31) == 0) red[tid >> 5] = acc;
    __syncthreads();
    if (tid == 0) {
        float t = 0.f;
        #pragma unroll
        for (int i = 0; i < 16; i++) t += red[i];
        out[blockIdx.x] = t;
    }
}

extern "C" void kernel_launch(void* const* d_in, const int* in_sizes, int n_in,
                              void* d_out, int out_size) {
    const float* x = (const float*)d_in[0];   // (256, 12) float32
    const float* w = (const float*)d_in[1];   // (96,)     float32
    float* out = (float*)d_out;               // (256, 1)  float32
    (void)in_sizes; (void)n_in; (void)out_size;
    cudaFuncSetAttribute(qsim_kernel, cudaFuncAttributeMaxDynamicSharedMemorySize,
                         2 * DIM * (int)sizeof(u64));
    qsim_kernel<<<256, NT, 2 * DIM * sizeof(u64)>>>(x, w, out);
}

// round 13
// speedup vs baseline: 1.0419x; 1.0419x over previous
#include <cuda_runtime.h>

// 12-qubit, 4-layer variational circuit simulator — R11.
// R7 (512thr/8amp) regressed to 40.6us due to register spills at the forced
// 64-reg cap (L1 70.7% = LDL/STL traffic). R11 keeps the 8-warps/SMSP plan but
// makes 64 regs sufficient:
//  - padded layout slot(i) = i + (i>>4) instead of XOR swizzle: every pass's
//    addresses are base + compile-time-constant offsets (k, 17k, 272k) ->
//    LDS [R+imm], no per-access address registers. Bank-conflict-free
//    (enumerated per half-warp) in all passes incl. the perm-fused gather.
//  - gate splats loaded from smem per stage in scoped blocks (transient regs)
//  - bases recomputed per pass; minimal persistent state
// Retained: f32x2 math, fused trainable-RZ pass diagonals, separable data
// diagonal, shfl-xor 4th qubit per pass, CX ladder fused into pass-A loads,
// ping-pong buffers, layer-0 from constant state, __launch_bounds__(512,2).

#define NT   512
#define PDIM 4352               // 4096 + 4096/16 padding slots
typedef unsigned long long u64;

__device__ __forceinline__ int slot(int i) { return i + (i >> 4); }

__device__ __forceinline__ u64 pk2(float lo, float hi) {
    u64 r;
    asm("mov.b64 %0, {%1, %2};" : "=l"(r)
        : "r"(__float_as_uint(lo)), "r"(__float_as_uint(hi)));
    return r;
}
__device__ __forceinline__ void upk(u64 v, float& lo, float& hi) {
    unsigned a, b;
    asm("mov.b64 {%0, %1}, %2;" : "=r"(a), "=r"(b) : "l"(v));
    lo = __uint_as_float(a);
    hi = __uint_as_float(b);
}
__device__ __forceinline__ u64 swp(u64 v) {
    unsigned a, b;
    asm("mov.b64 {%0, %1}, %2;" : "=r"(a), "=r"(b) : "l"(v));
    u64 r;
    asm("mov.b64 %0, {%1, %2};" : "=l"(r) : "r"(b), "r"(a));
    return r;
}
__device__ __forceinline__ u64 mul2(u64 a, u64 b) {
    u64 r;
    asm("mul.rn.f32x2 %0, %1, %2;" : "=l"(r) : "l"(a), "l"(b));
    return r;
}
__device__ __forceinline__ u64 fma2(u64 a, u64 b, u64 c) {
    u64 r;
    asm("fma.rn.f32x2 %0, %1, %2, %3;" : "=l"(r) : "l"(a), "l"(b), "l"(c));
    return r;
}
// a * (pr + i*pi); phase pre-splatted r2=(pr,pr), n=(-pi,pi); a packed (re,im).
__device__ __forceinline__ u64 pmul(u64 a, u64 r2, u64 n) {
    return fma2(r2, a, mul2(n, swp(a)));
}

struct GY { u64 c2, s2, ns2; };  // (c,c) (s,s) (-s,-s)

__device__ __forceinline__ void ry2(u64& a0, u64& a1, u64 c2, u64 s2, u64 ns2) {
    u64 t0 = fma2(c2, a0, mul2(ns2, a1));
    u64 t1 = fma2(s2, a0, mul2(c2, a1));
    a0 = t0; a1 = t1;
}
// RYs on the 3 k-bits of a[8]; gates loaded per stage to bound liveness.
__device__ __forceinline__ void ry3(u64* a, const GY* gs) {
    {
        GY g = gs[0];
        #pragma unroll
        for (int k = 0; k < 8; k += 2) ry2(a[k], a[k + 1], g.c2, g.s2, g.ns2);
    }
    {
        GY g = gs[1];
        #pragma unroll
        for (int k = 0; k < 8; k++) if (!(k & 2)) ry2(a[k], a[k | 2], g.c2, g.s2, g.ns2);
    }
    {
        GY g = gs[2];
        #pragma unroll
        for (int k = 0; k < 4; k++) ry2(a[k], a[k | 4], g.c2, g.s2, g.ns2);
    }
}
// RY on a lane-bit qubit via shfl_xor; ss picked by this thread's side.
__device__ __forceinline__ void rysh(u64* a, const GY* g, int side, unsigned m) {
    u64 c2 = g->c2;
    u64 ss = side ? g->s2 : g->ns2;
    #pragma unroll
    for (int k = 0; k < 8; k++) {
        u64 p = __shfl_xor_sync(0xffffffffu, a[k], m);
        a[k] = fma2(c2, a[k], mul2(ss, p));
    }
}
// Fused trainable-RZ diagonal for a pass; dP already offset by (side<<3).
__device__ __forceinline__ void diag8(u64* a, const ulonglong2* dP) {
    #pragma unroll
    for (int k = 0; k < 8; k++) { ulonglong2 d = dP[k]; a[k] = pmul(a[k], d.x, d.y); }
}

__global__ void __launch_bounds__(NT, 2)
qsim_kernel(const float* __restrict__ x, const float* __restrict__ w,
            float* __restrict__ out) {
    extern __shared__ u64 amp[];        // [2][PDIM] ping-pong, padded layout
    __shared__ GY gy[48];               // RY splats
    __shared__ ulonglong2 gd[12 * 16];  // fused-RZ diag splats per (layer,pass)
    __shared__ ulonglong2 tl[64];       // data-diag qubits 0..5 splats
    __shared__ ulonglong2 th[64];       // data-diag qubits 6..11 splats
    __shared__ float red[16];

    const int tid = threadIdx.x;

    // ---- precompute: one sincos per thread-slot ----
    if (tid < 48) {                               // RY gate splats
        float c, s;
        sincosf(0.5f * w[2 * tid], &s, &c);
        gy[tid].c2 = pk2(c, c);
        gy[tid].s2 = pk2(s, s);
        gy[tid].ns2 = pk2(-s, -s);
    }
    if (tid >= 64 && tid < 192) {                 // separable data-diagonal tables
        const float* xv = x + blockIdx.x * 12;
        int m = (tid - 64) & 63;
        const float* xs = xv + ((tid < 128) ? 6 : 0);   // 64..127 -> th, 128..191 -> tl
        float a = 0.f;
        #pragma unroll
        for (int q = 0; q < 6; q++) a += ((m >> q) & 1) ? xs[q] : -xs[q];
        a *= 0.5f;
        float sn, cs;
        sincosf(a, &sn, &cs);
        ulonglong2 e = make_ulonglong2(pk2(cs, cs), pk2(-sn, sn));
        if (tid < 128) th[m] = e; else tl[m] = e;
    }
    if (tid >= 192 && tid < 384) {                // fused trainable-RZ diagonals
        int idx = tid - 192;
        int p = idx >> 4, m = idx & 15;           // p = layer*3 + subpass
        int layer = p / 3, qb = (p % 3) * 4;
        const float* wz = w + 2 * (layer * 12 + qb);
        float t = 0.f;
        #pragma unroll
        for (int j = 0; j < 4; j++)
            t += (((m >> j) & 1) ? 0.5f : -0.5f) * wz[2 * j + 1];
        float di, dr;
        sincosf(t, &di, &dr);
        gd[idx] = make_ulonglong2(pk2(dr, dr), pk2(-di, di));
    }
    __syncthreads();

    // pass mappings (i = state index, t = tid, k = 0..7):
    //  A: i = (t<<3)|k                      local q0,1,2; shfl q3 <-> t bit0
    //     slot = 8t + (t>>1) + k
    //  B: i = (t&15)|(k<<4)|((t>>4)<<7)     local q4,5,6; shfl q7 <-> t bit4
    //     slot = (t&15) + 136*(t>>4) + 17k
    //  C: i = (t&15)|(((t>>5)&15)<<4)|(k<<8)|(((t>>4)&1)<<11)
    //     local q8,9,10; shfl q11 <-> t bit4
    //     slot = (t&15) + 17*((t>>5)&15) + 2176*((t>>4)&1) + 272k
    u64* const buf0 = amp;
    u64* const buf1 = amp + PDIM;
    u64 a[8];

    // ---- layer 0, pass A: const state * data diag, RY q0..2, shfl q3, RZ diag ----
    {
        const ulonglong2 hsp = th[tid >> 3];      // i>>6 data phase, thread-constant
        const u64 C = pk2(0.015625f, 0.f);
        #pragma unroll
        for (int k = 0; k < 8; k++) {
            ulonglong2 t = tl[((tid & 7) << 3) | k];
            a[k] = pmul(pmul(C, t.x, t.y), hsp.x, hsp.y);
        }
        ry3(a, gy);
        rysh(a, gy + 3, tid & 1, 1u);
        diag8(a, gd + ((tid & 1) << 3));
        const int b = (tid << 3) + (tid >> 1);
        #pragma unroll
        for (int k = 0; k < 8; k++) buf0[b + k] = a[k];
        __syncthreads();
    }

    #pragma unroll
    for (int l = 0; l < 4; l++) {
        u64* const cur = (l & 1) ? buf1 : buf0;
        const GY* g = gy + l * 12;

        // ---- pass B: qubits 4..7, in place ----
        {
            const int b = (tid & 15) + 136 * (tid >> 4);
            #pragma unroll
            for (int k = 0; k < 8; k++) a[k] = cur[b + 17 * k];
            ry3(a, g + 4);
            rysh(a, g + 7, (tid >> 4) & 1, 16u);
            diag8(a, gd + (l * 3 + 1) * 16 + (((tid >> 4) & 1) << 3));
            #pragma unroll
            for (int k = 0; k < 8; k++) cur[b + 17 * k] = a[k];
        }
        __syncthreads();

        // ---- pass C: qubits 8..11, in place ----
        {
            const int b = (tid & 15) + 17 * ((tid >> 5) & 15) + 2176 * ((tid >> 4) & 1);
            #pragma unroll
            for (int k = 0; k < 8; k++) a[k] = cur[b + 272 * k];
            ry3(a, g + 8);
            rysh(a, g + 11, (tid >> 4) & 1, 16u);
            diag8(a, gd + (l * 3 + 2) * 16 + (((tid >> 4) & 1) << 3));
            #pragma unroll
            for (int k = 0; k < 8; k++) cur[b + 272 * k] = a[k];
        }
        __syncthreads();

        // ---- next layer pass A: CX-perm gather from cur -> write other buffer ----
        if (l < 3) {
            u64* const nxt = (l & 1) ? buf0 : buf1;
            #pragma unroll
            for (int k = 0; k < 8; k++) {
                int i = (tid << 3) | k;
                int j = i ^ ((i << 1) & 0xFFE);   // composed CX ladder
                a[k] = cur[slot(j)];
            }
            const ulonglong2 hsp = th[tid >> 3];
            #pragma unroll
            for (int k = 0; k < 8; k++) {
                ulonglong2 t = tl[((tid & 7) << 3) | k];
                a[k] = pmul(pmul(a[k], t.x, t.y), hsp.x, hsp.y);
            }
            ry3(a, g + 12);
            rysh(a, g + 15, tid & 1, 1u);
            diag8(a, gd + (l + 1) * 3 * 16 + ((tid & 1) << 3));
            const int b = (tid << 3) + (tid >> 1);
            #pragma unroll
            for (int k = 0; k < 8; k++) nxt[b + k] = a[k];
            __syncthreads();
        }
    }

    // ---- measurement: <Z(0)> with final CX-perm fused into the load ----
    float acc = 0.f;
    #pragma unroll
    for (int k = 0; k < 8; k++) {
        int i = (tid << 3) | k;
        int j = i ^ ((i << 1) & 0xFFE);
        float re, im;
        upk(buf1[slot(j)], re, im);
        float p = re * re + im * im;
        acc += (k & 1) ? -p : p;
    }
    #pragma unroll
    for (int off = 16; off > 0; off >>= 1)
        acc += __shfl_down_sync(0xffffffffu, acc, off);
    if ((tid & 31) == 0) red[tid >> 5] = acc;
    __syncthreads();
    if (tid == 0) {
        float t = 0.f;
        #pragma unroll
        for (int i = 0; i < 16; i++) t += red[i];
        out[blockIdx.x] = t;
    }
}

extern "C" void kernel_launch(void* const* d_in, const int* in_sizes, int n_in,
                              void* d_out, int out_size) {
    const float* x = (const float*)d_in[0];   // (256, 12) float32
    const float* w = (const float*)d_in[1];   // (96,)     float32
    float* out = (float*)d_out;               // (256, 1)  float32
    (void)in_sizes; (void)n_in; (void)out_size;
    cudaFuncSetAttribute(qsim_kernel, cudaFuncAttributeMaxDynamicSharedMemorySize,
                         2 * PDIM * (int)sizeof(u64));
    qsim_kernel<<<256, NT, 2 * PDIM * sizeof(u64)>>>(x, w, out);
}

// round 15
// speedup vs baseline: 1.8526x; 1.7781x over previous
#include <cuda_runtime.h>

// 12-qubit, 4-layer variational circuit simulator — R13.
// R7/R11 (shfl-based) regressed: SHFL is MIO traffic, doubling L1 pressure/amp.
// R13 reverts to R5's 16-amps/256-threads structure (no shfl) and attacks R5's
// real limiter (barrier phase-locking, issue 35.7%):
//  - passes B and C operate on the SAME warp-private 512-amp set
//    {i : bits0-3 in {2w,2w+1}} -> B->C is just __syncwarp()
//  - per layer: permA -> syncthreads, B -> syncwarp, C -> syncthreads
//    (2 full barriers/layer instead of ~5)
//  - two-level padded layout slot(i) = i + (i>>4) + (i>>8): pass strides
//    1 / 17 / 273 (u64) all bank-stride 2 mod 32 -> conflict-free LDS/STS
//  - ping-pong buffers so the CX-perm gather needs one barrier
// Retained: packed f32x2 gate math, fused trainable-RZ pass diagonals,
// separable data diagonal, CX ladder fused into gathers, layer-0 from the
// constant state, __launch_bounds__(256,2).

#define NT   256
#define PDIM 4368               // slot(4095)=4365 -> round up
typedef unsigned long long u64;

__device__ __forceinline__ int slot(int i) { return i + (i >> 4) + (i >> 8); }

__device__ __forceinline__ u64 pk2(float lo, float hi) {
    u64 r;
    asm("mov.b64 %0, {%1, %2};" : "=l"(r)
        : "r"(__float_as_uint(lo)), "r"(__float_as_uint(hi)));
    return r;
}
__device__ __forceinline__ void upk(u64 v, float& lo, float& hi) {
    unsigned a, b;
    asm("mov.b64 {%0, %1}, %2;" : "=r"(a), "=r"(b) : "l"(v));
    lo = __uint_as_float(a);
    hi = __uint_as_float(b);
}
__device__ __forceinline__ u64 swp(u64 v) {
    unsigned a, b;
    asm("mov.b64 {%0, %1}, %2;" : "=r"(a), "=r"(b) : "l"(v));
    u64 r;
    asm("mov.b64 %0, {%1, %2};" : "=l"(r) : "r"(b), "r"(a));
    return r;
}
__device__ __forceinline__ u64 mul2(u64 a, u64 b) {
    u64 r;
    asm("mul.rn.f32x2 %0, %1, %2;" : "=l"(r) : "l"(a), "l"(b));
    return r;
}
__device__ __forceinline__ u64 fma2(u64 a, u64 b, u64 c) {
    u64 r;
    asm("fma.rn.f32x2 %0, %1, %2, %3;" : "=l"(r) : "l"(a), "l"(b), "l"(c));
    return r;
}
// a * (pr + i*pi); phase pre-splatted r2=(pr,pr), n=(-pi,pi); a packed (re,im).
__device__ __forceinline__ u64 pmul(u64 a, u64 r2, u64 n) {
    return fma2(r2, a, mul2(n, swp(a)));
}

struct GY { u64 c2, s2, ns2; };  // (c,c) (s,s) (-s,-s)

__device__ __forceinline__ void ry2(u64& a0, u64& a1, u64 c2, u64 s2, u64 ns2) {
    u64 t0 = fma2(c2, a0, mul2(ns2, a1));
    u64 t1 = fma2(s2, a0, mul2(c2, a1));
    a0 = t0; a1 = t1;
}
// RYs on the 4 k-bits of a[16]; gates loaded per stage (bounded liveness).
__device__ __forceinline__ void ry4(u64* a, const GY* gs) {
    {
        GY g = gs[0];
        #pragma unroll
        for (int k = 0; k < 16; k += 2) ry2(a[k], a[k + 1], g.c2, g.s2, g.ns2);
    }
    {
        GY g = gs[1];
        #pragma unroll
        for (int k = 0; k < 16; k++) if (!(k & 2)) ry2(a[k], a[k | 2], g.c2, g.s2, g.ns2);
    }
    {
        GY g = gs[2];
        #pragma unroll
        for (int k = 0; k < 16; k++) if (!(k & 4)) ry2(a[k], a[k | 4], g.c2, g.s2, g.ns2);
    }
    {
        GY g = gs[3];
        #pragma unroll
        for (int k = 0; k < 8; k++) ry2(a[k], a[k | 8], g.c2, g.s2, g.ns2);
    }
}
// Fused trainable-RZ diagonal for a pass (16 entries indexed by k).
__device__ __forceinline__ void diag16(u64* a, const ulonglong2* dP) {
    #pragma unroll
    for (int k = 0; k < 16; k++) { ulonglong2 d = dP[k]; a[k] = pmul(a[k], d.x, d.y); }
}

__global__ void __launch_bounds__(NT, 2)
qsim_kernel(const float* __restrict__ x, const float* __restrict__ w,
            float* __restrict__ out) {
    extern __shared__ u64 amp[];        // [2][PDIM] ping-pong, padded layout
    __shared__ GY gy[48];               // RY splats
    __shared__ ulonglong2 gd[12 * 16];  // fused-RZ diag splats per (layer,pass)
    __shared__ ulonglong2 tlP[64];      // data-diag qubits 0..5 splats, permuted
    __shared__ ulonglong2 th[64];       // data-diag qubits 6..11 splats
    __shared__ float red[8];

    const int tid = threadIdx.x;

    // ---- precompute (one/few sincos per thread) ----
    if (tid < 48) {                               // RY gate splats
        float c, s;
        sincosf(0.5f * w[2 * tid], &s, &c);
        gy[tid].c2 = pk2(c, c);
        gy[tid].s2 = pk2(s, s);
        gy[tid].ns2 = pk2(-s, -s);
    }
    if (tid < 192) {                              // fused trainable-RZ diagonals
        int p = tid >> 4, m = tid & 15;           // p = layer*3 + subpass
        int layer = p / 3, qb = (p % 3) * 4;
        const float* wz = w + 2 * (layer * 12 + qb);
        float t = 0.f;
        #pragma unroll
        for (int j = 0; j < 4; j++)
            t += (((m >> j) & 1) ? 0.5f : -0.5f) * wz[2 * j + 1];
        float di, dr;
        sincosf(t, &di, &dr);
        gd[tid] = make_ulonglong2(pk2(dr, dr), pk2(-di, di));
    }
    if (tid >= 64 && tid < 192) {                 // separable data-diagonal tables
        const float* xv = x + blockIdx.x * 12;
        int m = (tid - 64) & 63;
        const float* xs = xv + ((tid < 128) ? 6 : 0);   // 64..127 -> th, 128..191 -> tlP
        float a = 0.f;
        #pragma unroll
        for (int q = 0; q < 6; q++) a += ((m >> q) & 1) ? xs[q] : -xs[q];
        a *= 0.5f;
        float sn, cs;
        sincosf(a, &sn, &cs);
        ulonglong2 e = make_ulonglong2(pk2(cs, cs), pk2(-sn, sn));
        if (tid < 128) th[m] = e;
        else           tlP[((m & 15) << 2) | (m >> 4)] = e;
    }
    __syncthreads();

    // pass mappings (i = state index, t = tid, k = 0..15, slot = i+(i>>4)+(i>>8)):
    //  A: i = (t<<4)|k            -> slot = 17t + (t>>4) + k
    //  B: i = c | (k<<4) | (h<<8) -> slot = c + 273h + 17k
    //  C: i = c | (h<<4) | (k<<8) -> slot = c + 17h  + 273k
    //  with c = 2*(t>>5) + ((t>>4)&1)  (warp-private bits0-3 pair), h = t&15.
    //  Warp w owns {i : bits0-3 in {2w,2w+1}} in BOTH B and C -> syncwarp between.
    const int c16 = 2 * (tid >> 5) + ((tid >> 4) & 1);
    const int h16 = tid & 15;
    const int sA  = 17 * tid + (tid >> 4);
    const int sB  = c16 + 273 * h16;
    const int sC  = c16 + 17 * h16;

    u64* const buf0 = amp;
    u64* const buf1 = amp + PDIM;
    u64 a[16];

    // ---- layer 0, pass A: const state * data diag, RY q0..3, RZ diag ----
    {
        const ulonglong2 hsp = th[tid >> 2];      // i>>6 data phase, thread-constant
        const u64 C = pk2(0.015625f, 0.f);
        #pragma unroll
        for (int k = 0; k < 16; k++) {
            ulonglong2 t = tlP[(k << 2) | (tid & 3)];
            a[k] = pmul(pmul(C, t.x, t.y), hsp.x, hsp.y);
        }
        ry4(a, gy);
        diag16(a, gd);
        #pragma unroll
        for (int k = 0; k < 16; k++) buf0[sA + k] = a[k];
        __syncthreads();
    }

    #pragma unroll
    for (int l = 0; l < 4; l++) {
        u64* const cur = (l & 1) ? buf1 : buf0;
        const GY* g = gy + l * 12;

        // ---- pass B: qubits 4..7, in place on warp-private set ----
        #pragma unroll
        for (int k = 0; k < 16; k++) a[k] = cur[sB + 17 * k];
        ry4(a, g + 4);
        diag16(a, gd + (l * 3 + 1) * 16);
        #pragma unroll
        for (int k = 0; k < 16; k++) cur[sB + 17 * k] = a[k];
        __syncwarp();

        // ---- pass C: qubits 8..11, in place on the SAME warp-private set ----
        #pragma unroll
        for (int k = 0; k < 16; k++) a[k] = cur[sC + 273 * k];
        ry4(a, g + 8);
        diag16(a, gd + (l * 3 + 2) * 16);
        #pragma unroll
        for (int k = 0; k < 16; k++) cur[sC + 273 * k] = a[k];
        __syncthreads();

        // ---- next layer pass A: CX-perm gather cur -> write other buffer ----
        if (l < 3) {
            u64* const nxt = (l & 1) ? buf0 : buf1;
            #pragma unroll
            for (int k = 0; k < 16; k++) {
                int i = (tid << 4) | k;
                int j = i ^ ((i << 1) & 0xFFE);   // composed CX ladder
                a[k] = cur[slot(j)];
            }
            const ulonglong2 hsp = th[tid >> 2];
            #pragma unroll
            for (int k = 0; k < 16; k++) {
                ulonglong2 t = tlP[(k << 2) | (tid & 3)];
                a[k] = pmul(pmul(a[k], t.x, t.y), hsp.x, hsp.y);
            }
            ry4(a, g + 12);
            diag16(a, gd + (l + 1) * 3 * 16);
            #pragma unroll
            for (int k = 0; k < 16; k++) nxt[sA + k] = a[k];
            __syncthreads();
        }
    }

    // ---- measurement: <Z(0)>, final CX-perm fused into the load (state in buf1) ----
    float acc = 0.f;
    #pragma unroll
    for (int k = 0; k < 16; k++) {
        int i = (tid << 4) | k;
        int j = i ^ ((i << 1) & 0xFFE);
        float re, im;
        upk(buf1[slot(j)], re, im);
        float p = re * re + im * im;
        acc += (k & 1) ? -p : p;
    }
    #pragma unroll
    for (int off = 16; off > 0; off >>= 1)
        acc += __shfl_down_sync(0xffffffffu, acc, off);
    if ((tid & 31) == 0) red[tid >> 5] = acc;
    __syncthreads();
    if (tid == 0) {
        float t = 0.f;
        #pragma unroll
        for (int i = 0; i < 8; i++) t += red[i];
        out[blockIdx.x] = t;
    }
}

extern "C" void kernel_launch(void* const* d_in, const int* in_sizes, int n_in,
                              void* d_out, int out_size) {
    const float* x = (const float*)d_in[0];   // (256, 12) float32
    const float* w = (const float*)d_in[1];   // (96,)     float32
    float* out = (float*)d_out;               // (256, 1)  float32
    (void)in_sizes; (void)n_in; (void)out_size;
    cudaFuncSetAttribute(qsim_kernel, cudaFuncAttributeMaxDynamicSharedMemorySize,
                         2 * PDIM * (int)sizeof(u64));
    qsim_kernel<<<256, NT, 2 * PDIM * sizeof(u64)>>>(x, w, out);
}